// round 2
// baseline (speedup 1.0000x reference)
#include <cuda_runtime.h>
#include <math.h>

// Problem dims
#define BB   32
#define SS   1024
#define DD   512
#define NHEAD 16
#define NBLK 12
#define DHD  32
#define FFD  2048
#define MR   (BB*SS)   // 32768 rows

// ---------------- scratch (device globals; no allocs allowed) ----------------
__device__ float g_x[MR * DD];       // block input / output
__device__ float g_y[MR * DD];       // post-attn / post-LN1
__device__ float g_heads[MR * DD];   // concatenated head outputs
__device__ float g_qkv[MR * 96];     // per-head qkv projection
__device__ float g_ff[MR * FFD];     // FFN intermediate

// ---------------- embedding + positional encoding ----------------
__global__ void embed_kernel(const int* __restrict__ tok,
                             const float* __restrict__ emb) {
    int bs = blockIdx.x;              // 0..MR-1
    int s  = bs & (SS - 1);
    int t  = tok[bs];
    const float* e = emb + (long)t * DD;
    float* out = g_x + (long)bs * DD;
    for (int d = threadIdx.x; d < DD; d += blockDim.x) {
        int i2 = d & ~1;
        float freq = powf(10000.0f, -(float)i2 / (float)DD);
        float ang = (float)s * freq;
        float pe = (d & 1) ? cosf(ang) : sinf(ang);
        out[d] = e[d] + pe;
    }
}

// ---------------- generic fp32 GEMM: C = A@B + bias (+relu) (+resid) --------
// BM=128, BN=64, BK=16, 256 threads, 8x4 per thread.
template<bool RELU, bool RESID>
__global__ __launch_bounds__(256)
void gemm_kernel(const float* __restrict__ A, int lda,
                 const float* __restrict__ Bm, int ldb,
                 const float* __restrict__ bias,
                 const float* __restrict__ Rm, int ldr,
                 float* __restrict__ C, int ldc,
                 int N, int K) {
    const int BM = 128, BN = 64, BK = 16;
    __shared__ float As[BK][BM];
    __shared__ float Bs[BK][BN];

    int tid = threadIdx.x;
    int tx = tid & 15;        // col group -> cols tx*4..+3
    int ty = tid >> 4;        // row group -> rows ty*8..+7
    int rowBase = blockIdx.y * BM;
    int colBase = blockIdx.x * BN;

    float acc[8][4];
#pragma unroll
    for (int i = 0; i < 8; i++)
#pragma unroll
        for (int j = 0; j < 4; j++) acc[i][j] = 0.f;

    int ar = tid >> 2;              // 0..63
    int ac = (tid & 3) * 4;         // 0,4,8,12
    int br = tid >> 4;              // 0..15
    int bc = (tid & 15) * 4;        // 0..60

    for (int kt = 0; kt < K; kt += BK) {
        // load A tile (transpose into As[k][row])
#pragma unroll
        for (int rr = 0; rr < 2; rr++) {
            int r = ar + rr * 64;
            const float* ap = A + (long)(rowBase + r) * lda + kt + ac;
            float4 v = *(const float4*)ap;
            As[ac + 0][r] = v.x; As[ac + 1][r] = v.y;
            As[ac + 2][r] = v.z; As[ac + 3][r] = v.w;
        }
        // load B tile
        {
            int gcol = colBase + bc;
            const float* bp = Bm + (long)(kt + br) * ldb + gcol;
            float4 v;
            if (gcol + 3 < N) {
                v = *(const float4*)bp;
            } else {
                v.x = (gcol + 0 < N) ? bp[0] : 0.f;
                v.y = (gcol + 1 < N) ? bp[1] : 0.f;
                v.z = (gcol + 2 < N) ? bp[2] : 0.f;
                v.w = (gcol + 3 < N) ? bp[3] : 0.f;
            }
            *(float4*)&Bs[br][bc] = v;
        }
        __syncthreads();
#pragma unroll
        for (int k = 0; k < BK; k++) {
            float a[8], b[4];
            *(float4*)&a[0] = *(const float4*)&As[k][ty * 8];
            *(float4*)&a[4] = *(const float4*)&As[k][ty * 8 + 4];
            *(float4*)&b[0] = *(const float4*)&Bs[k][tx * 4];
#pragma unroll
            for (int i = 0; i < 8; i++)
#pragma unroll
                for (int j = 0; j < 4; j++)
                    acc[i][j] += a[i] * b[j];
        }
        __syncthreads();
    }
    // epilogue
#pragma unroll
    for (int i = 0; i < 8; i++) {
        int row = rowBase + ty * 8 + i;
#pragma unroll
        for (int j = 0; j < 4; j++) {
            int col = colBase + tx * 4 + j;
            if (col < N) {
                float v = acc[i][j] + bias[col];
                if (RELU) v = fmaxf(v, 0.f);
                if (RESID) v += Rm[(long)row * ldr + col];
                C[(long)row * ldc + col] = v;
            }
        }
    }
}

// ---------------- fused flash-style attention (one head, DH=32) -------------
// grid (S/128, B), 128 threads; thread t handles q row qbase+t; online softmax.
__global__ __launch_bounds__(128)
void attn_kernel(int head_off) {
    __shared__ float Ks[128][DHD];
    __shared__ float Vs[128][DHD];
    int b = blockIdx.y;
    int q = blockIdx.x * 128 + threadIdx.x;
    const float* qp = g_qkv + ((long)(b * SS) + q) * 96;
    float qr[DHD];
#pragma unroll
    for (int d = 0; d < DHD; d += 4)
        *(float4*)&qr[d] = *(const float4*)(qp + d);
    const float scale = 0.03125f;   // 1/sqrt(1024)
#pragma unroll
    for (int d = 0; d < DHD; d++) qr[d] *= scale;

    float m = -1e30f, l = 0.f;
    float o[DHD];
#pragma unroll
    for (int d = 0; d < DHD; d++) o[d] = 0.f;

    for (int kt = 0; kt < SS; kt += 128) {
        __syncthreads();
        {
            const float* kp = g_qkv + ((long)(b * SS) + kt + threadIdx.x) * 96;
#pragma unroll
            for (int d = 0; d < DHD; d += 4) {
                *(float4*)&Ks[threadIdx.x][d] = *(const float4*)(kp + 32 + d);
                *(float4*)&Vs[threadIdx.x][d] = *(const float4*)(kp + 64 + d);
            }
        }
        __syncthreads();
#pragma unroll 4
        for (int j = 0; j < 128; j++) {
            const float* kr = Ks[j];
            float s0 = 0.f, s1 = 0.f, s2 = 0.f, s3 = 0.f;
#pragma unroll
            for (int d = 0; d < DHD; d += 4) {
                s0 += qr[d + 0] * kr[d + 0];
                s1 += qr[d + 1] * kr[d + 1];
                s2 += qr[d + 2] * kr[d + 2];
                s3 += qr[d + 3] * kr[d + 3];
            }
            float sc = (s0 + s1) + (s2 + s3);
            float p;
            if (sc > m) {                 // rare after warm-up
                float cf = __expf(m - sc);
                l *= cf;
#pragma unroll
                for (int d = 0; d < DHD; d++) o[d] *= cf;
                m = sc;
                p = 1.f;
            } else {
                p = __expf(sc - m);
            }
            l += p;
            const float* vr = Vs[j];
#pragma unroll
            for (int d = 0; d < DHD; d++) o[d] += p * vr[d];
        }
    }
    float inv = 1.f / l;
    float* op = g_heads + ((long)(b * SS) + q) * DD + head_off;
#pragma unroll
    for (int d = 0; d < DHD; d++) op[d] = o[d] * inv;
}

// ---------------- LayerNorm (in place), warp per row -------------------------
__global__ __launch_bounds__(256)
void ln_kernel(float* __restrict__ X, const float* __restrict__ g,
               const float* __restrict__ bb) {
    int warp = threadIdx.x >> 5;
    int lane = threadIdx.x & 31;
    int row = blockIdx.x * 8 + warp;
    float* xp = X + (long)row * DD;
    float v[16];
    float sum = 0.f;
#pragma unroll
    for (int w = 0; w < 4; w++) {
        float4 t = *(const float4*)(xp + lane * 4 + w * 128);
        v[w * 4 + 0] = t.x; v[w * 4 + 1] = t.y;
        v[w * 4 + 2] = t.z; v[w * 4 + 3] = t.w;
        sum += (t.x + t.y) + (t.z + t.w);
    }
#pragma unroll
    for (int off = 16; off; off >>= 1) sum += __shfl_xor_sync(~0u, sum, off);
    float mean = sum * (1.f / (float)DD);
    float var = 0.f;
#pragma unroll
    for (int i = 0; i < 16; i++) {
        float d = v[i] - mean;
        var += d * d;
    }
#pragma unroll
    for (int off = 16; off; off >>= 1) var += __shfl_xor_sync(~0u, var, off);
    var *= (1.f / (float)DD);
    float rs = rsqrtf(var + 1e-3f);
#pragma unroll
    for (int w = 0; w < 4; w++) {
#pragma unroll
        for (int j = 0; j < 4; j++) {
            int d = lane * 4 + w * 128 + j;
            xp[d] = (v[w * 4 + j] - mean) * rs * g[d] + bb[d];
        }
    }
}

// ---------------- mean-pool over S, final dense + sigmoid --------------------
__global__ __launch_bounds__(256)
void pool_kernel(const float* __restrict__ Wf, const float* __restrict__ bf,
                 float* __restrict__ out) {
    int b = blockIdx.x;
    const float* xp = g_x + (long)b * SS * DD;
    float partial = 0.f;
    for (int i = threadIdx.x; i < SS * DD; i += blockDim.x)
        partial += xp[i] * Wf[i & (DD - 1)];
    __shared__ float red[256];
    red[threadIdx.x] = partial;
    __syncthreads();
    for (int s = 128; s; s >>= 1) {
        if (threadIdx.x < s) red[threadIdx.x] += red[threadIdx.x + s];
        __syncthreads();
    }
    if (threadIdx.x == 0) {
        float z = red[0] * (1.f / (float)SS) + bf[0];
        out[b] = z;
        out[BB + b] = 1.f / (1.f + expf(-z));
    }
}

// ---------------- host orchestration -----------------------------------------
extern "C" void kernel_launch(void* const* d_in, const int* in_sizes, int n_in,
                              void* d_out, int out_size) {
    const int*   tokens = (const int*)  d_in[0];
    const float* emb    = (const float*)d_in[1];
    const float* W0     = (const float*)d_in[2];
    const float* b0     = (const float*)d_in[3];
    const float* Wh     = (const float*)d_in[4];
    const float* bh     = (const float*)d_in[5];
    const float* Wo     = (const float*)d_in[6];
    const float* bo     = (const float*)d_in[7];
    const float* g1     = (const float*)d_in[8];
    const float* be1    = (const float*)d_in[9];
    const float* W1     = (const float*)d_in[10];
    const float* b1     = (const float*)d_in[11];
    const float* W2     = (const float*)d_in[12];
    const float* b2     = (const float*)d_in[13];
    const float* g2     = (const float*)d_in[14];
    const float* be2    = (const float*)d_in[15];
    const float* Wf     = (const float*)d_in[16];
    const float* bf     = (const float*)d_in[17];
    float* out = (float*)d_out;

    float *gx, *gy, *gh, *gq, *gf;
    cudaGetSymbolAddress((void**)&gx, g_x);
    cudaGetSymbolAddress((void**)&gy, g_y);
    cudaGetSymbolAddress((void**)&gh, g_heads);
    cudaGetSymbolAddress((void**)&gq, g_qkv);
    cudaGetSymbolAddress((void**)&gf, g_ff);

    const int MTILES = MR / 128;   // 256

    embed_kernel<<<MR, 128>>>(tokens, emb);

    for (int l = 0; l < NBLK; l++) {
        // head 0 QKV: [MR,512] @ [512,96]
        gemm_kernel<false, false><<<dim3(2, MTILES), 256>>>(
            gx, DD, W0 + (long)l * DD * 96, 96, b0 + (long)l * 96,
            nullptr, 0, gq, 96, 96, DD);
        attn_kernel<<<dim3(SS / 128, BB), 128>>>(0);

        // chained heads 1..15: [MR,32] @ [32,96]
        for (int i = 0; i < NHEAD - 1; i++) {
            gemm_kernel<false, false><<<dim3(2, MTILES), 256>>>(
                gh + i * DHD, DD,
                Wh + ((long)l * (NHEAD - 1) + i) * DHD * 96, 96,
                bh + ((long)l * (NHEAD - 1) + i) * 96,
                nullptr, 0, gq, 96, 96, DHD);
            attn_kernel<<<dim3(SS / 128, BB), 128>>>((i + 1) * DHD);
        }

        // output projection + residual
        gemm_kernel<false, true><<<dim3(DD / 64, MTILES), 256>>>(
            gh, DD, Wo + (long)l * DD * DD, DD, bo + (long)l * DD,
            gx, DD, gy, DD, DD, DD);
        ln_kernel<<<MR / 8, 256>>>(gy, g1 + (long)l * DD, be1 + (long)l * DD);

        // FFN
        gemm_kernel<true, false><<<dim3(FFD / 64, MTILES), 256>>>(
            gy, DD, W1 + (long)l * DD * FFD, FFD, b1 + (long)l * FFD,
            nullptr, 0, gf, FFD, FFD, DD);
        gemm_kernel<false, true><<<dim3(DD / 64, MTILES), 256>>>(
            gf, FFD, W2 + (long)l * FFD * DD, DD, b2 + (long)l * DD,
            gy, DD, gx, DD, DD, FFD);
        ln_kernel<<<MR / 8, 256>>>(gx, g2 + (long)l * DD, be2 + (long)l * DD);
    }

    pool_kernel<<<BB, 256>>>(Wf, bf, out);
}

// round 7
// speedup vs baseline: 1.1182x; 1.1182x over previous
#include <cuda_runtime.h>
#include <math.h>

// Problem dims
#define BB   32
#define SS   1024
#define DD   512
#define NHEAD 16
#define NBLK 12
#define DHD  32
#define FFD  2048
#define MR   (BB*SS)   // 32768 rows

// ---------------- f32x2 packed helpers (SASS FFMA2 path) ----------------
typedef unsigned long long u64t;

__device__ __forceinline__ u64t pack2(float lo, float hi) {
    u64t r; asm("mov.b64 %0, {%1,%2};" : "=l"(r) : "f"(lo), "f"(hi)); return r;
}
__device__ __forceinline__ u64t fma2(u64t a, u64t b, u64t c) {
    u64t d; asm("fma.rn.f32x2 %0, %1, %2, %3;" : "=l"(d) : "l"(a), "l"(b), "l"(c)); return d;
}
__device__ __forceinline__ u64t add2(u64t a, u64t b) {
    u64t d; asm("add.rn.f32x2 %0, %1, %2;" : "=l"(d) : "l"(a), "l"(b)); return d;
}
__device__ __forceinline__ u64t mul2(u64t a, u64t b) {
    u64t d; asm("mul.rn.f32x2 %0, %1, %2;" : "=l"(d) : "l"(a), "l"(b)); return d;
}
__device__ __forceinline__ float2 unpack2(u64t v) {
    float2 f; asm("mov.b64 {%0,%1}, %2;" : "=f"(f.x), "=f"(f.y) : "l"(v)); return f;
}

// ---------------- scratch (device globals; no allocs allowed) ----------------
__device__ float g_x[MR * DD];       // block input / output
__device__ float g_y[MR * DD];       // post-attn / post-LN1
__device__ float g_heads[MR * DD];   // concatenated head outputs
__device__ float g_qkv[MR * 96];     // per-head qkv projection
__device__ float g_ff[MR * FFD];     // FFN intermediate

// ---------------- embedding + positional encoding ----------------
__global__ void embed_kernel(const int* __restrict__ tok,
                             const float* __restrict__ emb) {
    int bs = blockIdx.x;              // 0..MR-1
    int s  = bs & (SS - 1);
    int t  = tok[bs];
    const float* e = emb + (long)t * DD;
    float* out = g_x + (long)bs * DD;
    for (int d = threadIdx.x; d < DD; d += blockDim.x) {
        int i2 = d & ~1;
        float freq = powf(10000.0f, -(float)i2 / (float)DD);
        float ang = (float)s * freq;
        float pe = (d & 1) ? cosf(ang) : sinf(ang);
        out[d] = e[d] + pe;
    }
}

// ---------------- generic fp32 GEMM (f32x2 inner): C = A@B + bias (+relu)(+resid)
// BM=128, BN=64, BK=16, 256 threads; 8 rows x 4 cols per thread, rows paired.
template<bool RELU, bool RESID>
__global__ __launch_bounds__(256)
void gemm_kernel(const float* __restrict__ A, int lda,
                 const float* __restrict__ Bm, int ldb,
                 const float* __restrict__ bias,
                 const float* __restrict__ Rm, int ldr,
                 float* __restrict__ C, int ldc,
                 int N, int K) {
    const int BM = 128, BN = 64, BK = 16;
    __shared__ float As[BK][BM];
    __shared__ float Bs[BK][BN];

    int tid = threadIdx.x;
    int tx = tid & 15;        // col group -> cols tx*4..+3
    int ty = tid >> 4;        // row group -> rows ty*8..+7
    int rowBase = blockIdx.y * BM;
    int colBase = blockIdx.x * BN;

    // acc2[p][j]: packed rows (2p, 2p+1), column j
    u64t acc2[4][4];
#pragma unroll
    for (int p = 0; p < 4; p++)
#pragma unroll
        for (int j = 0; j < 4; j++) acc2[p][j] = 0ULL;

    int ar = tid >> 2;              // 0..63
    int ac = (tid & 3) * 4;         // 0,4,8,12
    int br = tid >> 4;              // 0..15
    int bc = (tid & 15) * 4;        // 0..60

    for (int kt = 0; kt < K; kt += BK) {
        // load A tile (transpose into As[k][row])
#pragma unroll
        for (int rr = 0; rr < 2; rr++) {
            int r = ar + rr * 64;
            const float* ap = A + (long)(rowBase + r) * lda + kt + ac;
            float4 v = *(const float4*)ap;
            As[ac + 0][r] = v.x; As[ac + 1][r] = v.y;
            As[ac + 2][r] = v.z; As[ac + 3][r] = v.w;
        }
        // load B tile
        {
            int gcol = colBase + bc;
            const float* bp = Bm + (long)(kt + br) * ldb + gcol;
            float4 v;
            if (gcol + 3 < N) {
                v = *(const float4*)bp;
            } else {
                v.x = (gcol + 0 < N) ? bp[0] : 0.f;
                v.y = (gcol + 1 < N) ? bp[1] : 0.f;
                v.z = (gcol + 2 < N) ? bp[2] : 0.f;
                v.w = (gcol + 3 < N) ? bp[3] : 0.f;
            }
            *(float4*)&Bs[br][bc] = v;
        }
        __syncthreads();
#pragma unroll
        for (int k = 0; k < BK; k++) {
            const ulonglong2* ap2 = (const ulonglong2*)&As[k][ty * 8];
            ulonglong2 a01 = ap2[0];     // rows pairs (0,1),(2,3)
            ulonglong2 a23 = ap2[1];     // rows pairs (4,5),(6,7)
            float4 b = *(const float4*)&Bs[k][tx * 4];
            u64t b0 = pack2(b.x, b.x);
            u64t b1 = pack2(b.y, b.y);
            u64t b2 = pack2(b.z, b.z);
            u64t b3 = pack2(b.w, b.w);
            acc2[0][0] = fma2(a01.x, b0, acc2[0][0]);
            acc2[0][1] = fma2(a01.x, b1, acc2[0][1]);
            acc2[0][2] = fma2(a01.x, b2, acc2[0][2]);
            acc2[0][3] = fma2(a01.x, b3, acc2[0][3]);
            acc2[1][0] = fma2(a01.y, b0, acc2[1][0]);
            acc2[1][1] = fma2(a01.y, b1, acc2[1][1]);
            acc2[1][2] = fma2(a01.y, b2, acc2[1][2]);
            acc2[1][3] = fma2(a01.y, b3, acc2[1][3]);
            acc2[2][0] = fma2(a23.x, b0, acc2[2][0]);
            acc2[2][1] = fma2(a23.x, b1, acc2[2][1]);
            acc2[2][2] = fma2(a23.x, b2, acc2[2][2]);
            acc2[2][3] = fma2(a23.x, b3, acc2[2][3]);
            acc2[3][0] = fma2(a23.y, b0, acc2[3][0]);
            acc2[3][1] = fma2(a23.y, b1, acc2[3][1]);
            acc2[3][2] = fma2(a23.y, b2, acc2[3][2]);
            acc2[3][3] = fma2(a23.y, b3, acc2[3][3]);
        }
        __syncthreads();
    }
    // epilogue
#pragma unroll
    for (int p = 0; p < 4; p++) {
#pragma unroll
        for (int j = 0; j < 4; j++) {
            float2 v2 = unpack2(acc2[p][j]);
            int col = colBase + tx * 4 + j;
            if (col < N) {
                int row0 = rowBase + ty * 8 + 2 * p;
                float v = v2.x + bias[col];
                float w = v2.y + bias[col];
                if (RELU) { v = fmaxf(v, 0.f); w = fmaxf(w, 0.f); }
                if (RESID) {
                    v += Rm[(long)row0 * ldr + col];
                    w += Rm[(long)(row0 + 1) * ldr + col];
                }
                C[(long)row0 * ldc + col] = v;
                C[(long)(row0 + 1) * ldc + col] = w;
            }
        }
    }
}

// ---------------- fused flash attention (one head, DH=32), f32x2 + 2-way KV split
// grid (S/128, B), 256 threads: qi = tid&127 (q row), sp = tid>>7 (KV half).
// Each split covers 512 keys in 8 tiles of 64; results merged in smem.
__global__ __launch_bounds__(256)
void attn_kernel(int head_off) {
    // buf layout: K tiles [0, 4096) = [sp*64 + r][32], V tiles [4096, 8192)
    // After main loop, buf[0,4096) is reused as combine buffer Co[128][32].
    __shared__ float buf[8192];          // 32 KB
    __shared__ float Cm[128], Cl[128];

    int tid = threadIdx.x;
    int qi = tid & 127;
    int sp = tid >> 7;                   // 0 or 1
    int b = blockIdx.y;
    int q = blockIdx.x * 128 + qi;

    // load + scale q (packed pairs)
    const float* qp = g_qkv + ((long)(b * SS) + q) * 96;
    u64t qr2[16];
    const float scale = 0.03125f;        // 1/sqrt(1024)
    u64t s2 = pack2(scale, scale);
#pragma unroll
    for (int i = 0; i < 8; i++) {
        ulonglong2 v = *(const ulonglong2*)(qp + i * 4);
        qr2[2 * i + 0] = mul2(v.x, s2);
        qr2[2 * i + 1] = mul2(v.y, s2);
    }

    float m = -1e30f, l = 0.f;
    u64t o2[16];
#pragma unroll
    for (int i = 0; i < 16; i++) o2[i] = 0ULL;

    int r = qi >> 1;                     // 0..63 tile row this thread loads
    int half = qi & 1;                   // which 16-float half

    for (int t = 0; t < 8; t++) {
        int kt0 = sp * 512 + t * 64;
        __syncthreads();
        {
            const float* kp = g_qkv + ((long)(b * SS) + kt0 + r) * 96;
            float* dk = &buf[(sp * 64 + r) * 32 + half * 16];
            float* dv = &buf[4096 + (sp * 64 + r) * 32 + half * 16];
#pragma unroll
            for (int w = 0; w < 4; w++) {
                *(float4*)(dk + w * 4) = *(const float4*)(kp + 32 + half * 16 + w * 4);
                *(float4*)(dv + w * 4) = *(const float4*)(kp + 64 + half * 16 + w * 4);
            }
        }
        __syncthreads();
#pragma unroll 2
        for (int j = 0; j < 64; j++) {
            const ulonglong2* kp2 = (const ulonglong2*)&buf[(sp * 64 + j) * 32];
            u64t sa = 0ULL, sb = 0ULL, sc2 = 0ULL, sd = 0ULL;
#pragma unroll
            for (int i = 0; i < 4; i++) {
                ulonglong2 k0 = kp2[2 * i];
                ulonglong2 k1 = kp2[2 * i + 1];
                sa = fma2(qr2[4 * i + 0], k0.x, sa);
                sb = fma2(qr2[4 * i + 1], k0.y, sb);
                sc2 = fma2(qr2[4 * i + 2], k1.x, sc2);
                sd = fma2(qr2[4 * i + 3], k1.y, sd);
            }
            float2 sf = unpack2(add2(add2(sa, sb), add2(sc2, sd)));
            float sc = sf.x + sf.y;
            float p;
            if (sc > m) {                 // rare after warm-up
                float cf = __expf(m - sc);
                l *= cf;
                u64t cf2 = pack2(cf, cf);
#pragma unroll
                for (int i = 0; i < 16; i++) o2[i] = mul2(o2[i], cf2);
                m = sc;
                p = 1.f;
            } else {
                p = __expf(sc - m);
            }
            l += p;
            u64t pp = pack2(p, p);
            const ulonglong2* vp2 = (const ulonglong2*)&buf[4096 + (sp * 64 + j) * 32];
#pragma unroll
            for (int i = 0; i < 8; i++) {
                ulonglong2 v = vp2[i];
                o2[2 * i + 0] = fma2(pp, v.x, o2[2 * i + 0]);
                o2[2 * i + 1] = fma2(pp, v.y, o2[2 * i + 1]);
            }
        }
    }

    // merge the two KV halves (reuse K region of buf as Co[128][32])
    __syncthreads();
    if (sp == 1) {
        Cm[qi] = m; Cl[qi] = l;
        float* co = &buf[qi * 32];
#pragma unroll
        for (int i = 0; i < 16; i++) {
            float2 v = unpack2(o2[i]);
            co[2 * i] = v.x; co[2 * i + 1] = v.y;
        }
    }
    __syncthreads();
    if (sp == 0) {
        float m1 = Cm[qi], l1 = Cl[qi];
        float M = fmaxf(m, m1);
        float c0 = __expf(m - M);
        float c1 = __expf(m1 - M);
        float inv = 1.f / (c0 * l + c1 * l1);
        const float* co = &buf[qi * 32];
        float* op = g_heads + ((long)(b * SS) + q) * DD + head_off;
#pragma unroll
        for (int i = 0; i < 16; i++) {
            float2 v = unpack2(o2[i]);
            op[2 * i]     = (c0 * v.x + c1 * co[2 * i]) * inv;
            op[2 * i + 1] = (c0 * v.y + c1 * co[2 * i + 1]) * inv;
        }
    }
}

// ---------------- LayerNorm (in place), warp per row -------------------------
__global__ __launch_bounds__(256)
void ln_kernel(float* __restrict__ X, const float* __restrict__ g,
               const float* __restrict__ bb) {
    int warp = threadIdx.x >> 5;
    int lane = threadIdx.x & 31;
    int row = blockIdx.x * 8 + warp;
    float* xp = X + (long)row * DD;
    float v[16];
    float sum = 0.f;
#pragma unroll
    for (int w = 0; w < 4; w++) {
        float4 t = *(const float4*)(xp + lane * 4 + w * 128);
        v[w * 4 + 0] = t.x; v[w * 4 + 1] = t.y;
        v[w * 4 + 2] = t.z; v[w * 4 + 3] = t.w;
        sum += (t.x + t.y) + (t.z + t.w);
    }
#pragma unroll
    for (int off = 16; off; off >>= 1) sum += __shfl_xor_sync(~0u, sum, off);
    float mean = sum * (1.f / (float)DD);
    float var = 0.f;
#pragma unroll
    for (int i = 0; i < 16; i++) {
        float d = v[i] - mean;
        var += d * d;
    }
#pragma unroll
    for (int off = 16; off; off >>= 1) var += __shfl_xor_sync(~0u, var, off);
    var *= (1.f / (float)DD);
    float rs = rsqrtf(var + 1e-3f);
#pragma unroll
    for (int w = 0; w < 4; w++) {
#pragma unroll
        for (int j = 0; j < 4; j++) {
            int d = lane * 4 + w * 128 + j;
            xp[d] = (v[w * 4 + j] - mean) * rs * g[d] + bb[d];
        }
    }
}

// ---------------- mean-pool over S, final dense + sigmoid --------------------
__global__ __launch_bounds__(256)
void pool_kernel(const float* __restrict__ Wf, const float* __restrict__ bf,
                 float* __restrict__ out) {
    int b = blockIdx.x;
    const float* xp = g_x + (long)b * SS * DD;
    float partial = 0.f;
    for (int i = threadIdx.x; i < SS * DD; i += blockDim.x)
        partial += xp[i] * Wf[i & (DD - 1)];
    __shared__ float red[256];
    red[threadIdx.x] = partial;
    __syncthreads();
    for (int s = 128; s; s >>= 1) {
        if (threadIdx.x < s) red[threadIdx.x] += red[threadIdx.x + s];
        __syncthreads();
    }
    if (threadIdx.x == 0) {
        float z = red[0] * (1.f / (float)SS) + bf[0];
        out[b] = z;
        out[BB + b] = 1.f / (1.f + expf(-z));
    }
}

// ---------------- host orchestration -----------------------------------------
extern "C" void kernel_launch(void* const* d_in, const int* in_sizes, int n_in,
                              void* d_out, int out_size) {
    const int*   tokens = (const int*)  d_in[0];
    const float* emb    = (const float*)d_in[1];
    const float* W0     = (const float*)d_in[2];
    const float* b0     = (const float*)d_in[3];
    const float* Wh     = (const float*)d_in[4];
    const float* bh     = (const float*)d_in[5];
    const float* Wo     = (const float*)d_in[6];
    const float* bo     = (const float*)d_in[7];
    const float* g1     = (const float*)d_in[8];
    const float* be1    = (const float*)d_in[9];
    const float* W1     = (const float*)d_in[10];
    const float* b1     = (const float*)d_in[11];
    const float* W2     = (const float*)d_in[12];
    const float* b2     = (const float*)d_in[13];
    const float* g2     = (const float*)d_in[14];
    const float* be2    = (const float*)d_in[15];
    const float* Wf     = (const float*)d_in[16];
    const float* bf     = (const float*)d_in[17];
    float* out = (float*)d_out;

    float *gx, *gy, *gh, *gq, *gf;
    cudaGetSymbolAddress((void**)&gx, g_x);
    cudaGetSymbolAddress((void**)&gy, g_y);
    cudaGetSymbolAddress((void**)&gh, g_heads);
    cudaGetSymbolAddress((void**)&gq, g_qkv);
    cudaGetSymbolAddress((void**)&gf, g_ff);

    const int MTILES = MR / 128;   // 256

    embed_kernel<<<MR, 128>>>(tokens, emb);

    for (int l = 0; l < NBLK; l++) {
        // head 0 QKV: [MR,512] @ [512,96]
        gemm_kernel<false, false><<<dim3(2, MTILES), 256>>>(
            gx, DD, W0 + (long)l * DD * 96, 96, b0 + (long)l * 96,
            nullptr, 0, gq, 96, 96, DD);
        attn_kernel<<<dim3(SS / 128, BB), 256>>>(0);

        // chained heads 1..15: [MR,32] @ [32,96]
        for (int i = 0; i < NHEAD - 1; i++) {
            gemm_kernel<false, false><<<dim3(2, MTILES), 256>>>(
                gh + i * DHD, DD,
                Wh + ((long)l * (NHEAD - 1) + i) * DHD * 96, 96,
                bh + ((long)l * (NHEAD - 1) + i) * 96,
                nullptr, 0, gq, 96, 96, DHD);
            attn_kernel<<<dim3(SS / 128, BB), 256>>>((i + 1) * DHD);
        }

        // output projection + residual
        gemm_kernel<false, true><<<dim3(DD / 64, MTILES), 256>>>(
            gh, DD, Wo + (long)l * DD * DD, DD, bo + (long)l * DD,
            gx, DD, gy, DD, DD, DD);
        ln_kernel<<<MR / 8, 256>>>(gy, g1 + (long)l * DD, be1 + (long)l * DD);

        // FFN
        gemm_kernel<true, false><<<dim3(FFD / 64, MTILES), 256>>>(
            gy, DD, W1 + (long)l * DD * FFD, FFD, b1 + (long)l * FFD,
            nullptr, 0, gf, FFD, FFD, DD);
        gemm_kernel<false, true><<<dim3(DD / 64, MTILES), 256>>>(
            gf, FFD, W2 + (long)l * FFD * DD, DD, b2 + (long)l * DD,
            gy, DD, gx, DD, DD, FFD);
        ln_kernel<<<MR / 8, 256>>>(gx, g2 + (long)l * DD, be2 + (long)l * DD);
    }

    pool_kernel<<<BB, 256>>>(Wf, bf, out);
}

// round 17
// speedup vs baseline: 1.1789x; 1.0543x over previous
#include <cuda_runtime.h>
#include <cuda_bf16.h>
#include <math.h>
#include <stdint.h>

// Problem dims
#define BB   32
#define SS   1024
#define DD   512
#define NHEAD 16
#define NBLK 12
#define DHD  32
#define FFD  2048
#define MR   (BB*SS)   // 32768 rows

// ---------------- f32x2 packed helpers (attention path) ----------------
typedef unsigned long long u64t;
__device__ __forceinline__ u64t pack2(float lo, float hi) {
    u64t r; asm("mov.b64 %0, {%1,%2};" : "=l"(r) : "f"(lo), "f"(hi)); return r;
}
__device__ __forceinline__ u64t fma2(u64t a, u64t b, u64t c) {
    u64t d; asm("fma.rn.f32x2 %0, %1, %2, %3;" : "=l"(d) : "l"(a), "l"(b), "l"(c)); return d;
}
__device__ __forceinline__ u64t add2(u64t a, u64t b) {
    u64t d; asm("add.rn.f32x2 %0, %1, %2;" : "=l"(d) : "l"(a), "l"(b)); return d;
}
__device__ __forceinline__ u64t mul2(u64t a, u64t b) {
    u64t d; asm("mul.rn.f32x2 %0, %1, %2;" : "=l"(d) : "l"(a), "l"(b)); return d;
}
__device__ __forceinline__ float2 unpack2(u64t v) {
    float2 f; asm("mov.b64 {%0,%1}, %2;" : "=f"(f.x), "=f"(f.y) : "l"(v)); return f;
}

// ---------------- scratch (device globals; no allocs allowed) ----------------
__device__ float g_x[MR * DD];       // block input / output
__device__ float g_y[MR * DD];       // post-attn / post-LN1
__device__ float g_heads[MR * DD];   // concatenated head outputs
__device__ float g_qkv[MR * 96];     // per-head qkv projection
__device__ float g_ff[MR * FFD];     // FFN intermediate

// ---------------- embedding + positional encoding ----------------
__global__ void embed_kernel(const int* __restrict__ tok,
                             const float* __restrict__ emb) {
    int bs = blockIdx.x;              // 0..MR-1
    int s  = bs & (SS - 1);
    int t  = tok[bs];
    const float* e = emb + (long)t * DD;
    float* out = g_x + (long)bs * DD;
    for (int d = threadIdx.x; d < DD; d += blockDim.x) {
        int i2 = d & ~1;
        float freq = powf(10000.0f, -(float)i2 / (float)DD);
        float ang = (float)s * freq;
        float pe = (d & 1) ? cosf(ang) : sinf(ang);
        out[d] = e[d] + pe;
    }
}

// =============================================================================
// Tensor-core GEMM via mma.sync bf16 (split hi/lo, 3-MMA emulation):
//   C = A@B + bias (+relu) (+resid)
// BM=128, BN=64, BK=32, 256 threads (8 warps, 4x2 grid of 32x32 warp tiles).
// A:[M,K] row-major; B:[K,N] row-major, transposed on SMEM store to [N,K].
// SMEM rows padded to 80B -> conflict-free fragment LDS.
// =============================================================================
#define SA_ST  80        // bytes per 32-element bf16 row (64B data + 16B pad)
#define SA_SZ  (128*SA_ST)          // 10240
#define SB_SZ  (64*SA_ST)           // 5120
#define OFF_AHI(b) ((b)*30720)
#define OFF_ALO(b) (OFF_AHI(b)+10240)
#define OFF_BHI(b) (OFF_AHI(b)+20480)
#define OFF_BLO(b) (OFF_AHI(b)+25600)
#define SMEM_GT 61440

__device__ __forceinline__ void mma16816(float* c, const uint32_t* a, const uint32_t* b) {
    asm volatile(
        "mma.sync.aligned.m16n8k16.row.col.f32.bf16.bf16.f32 "
        "{%0,%1,%2,%3}, {%4,%5,%6,%7}, {%8,%9}, {%0,%1,%2,%3};"
        : "+f"(c[0]), "+f"(c[1]), "+f"(c[2]), "+f"(c[3])
        : "r"(a[0]), "r"(a[1]), "r"(a[2]), "r"(a[3]), "r"(b[0]), "r"(b[1]));
}

__device__ __forceinline__ uint32_t bfpack(__nv_bfloat16 lo, __nv_bfloat16 hi) {
    __nv_bfloat162 v(lo, hi);
    return *(uint32_t*)&v;
}

template<bool RELU, bool RESID>
__global__ __launch_bounds__(256)
void gemm_tc(const float* __restrict__ A, int lda,
             const float* __restrict__ Bm, int ldb,
             const float* __restrict__ bias,
             const float* __restrict__ Rm, int ldr,
             float* __restrict__ C, int ldc,
             int N, int K) {
    extern __shared__ char sm[];
    int tid = threadIdx.x;
    int wid = tid >> 5, lane = tid & 31;
    int g = lane >> 2, tg = lane & 3;
    int warpRow = wid >> 1, warpCol = wid & 1;
    int rowBase = blockIdx.y * 128, colBase = blockIdx.x * 64;

    // accumulators: [mAtom(2)][nAtom(4)][4]
    float acc[2][4][4];
#pragma unroll
    for (int i = 0; i < 2; i++)
#pragma unroll
        for (int j = 0; j < 4; j++)
#pragma unroll
            for (int k = 0; k < 4; k++) acc[i][j][k] = 0.f;

    // global-load mapping
    int ar = tid >> 1, ah = (tid & 1) * 16;     // A: row, 16-col slab
    int brow = tid >> 3, bcol = (tid & 7) * 8;  // B: k-row, 8-col slab

    int nchunk = K >> 5;
    float av[16], bv[8];

    // ---- stage 0: load + convert + store chunk 0 ----
    {
        const float* ap = A + (long)(rowBase + ar) * lda + ah;
#pragma unroll
        for (int i = 0; i < 4; i++) {
            float4 v = *(const float4*)(ap + i * 4);
            av[i*4+0]=v.x; av[i*4+1]=v.y; av[i*4+2]=v.z; av[i*4+3]=v.w;
        }
        const float* bp = Bm + (long)brow * ldb + colBase + bcol;
#pragma unroll
        for (int i = 0; i < 8; i++)
            bv[i] = (colBase + bcol + i < N) ? bp[i] : 0.f;
    }

    for (int t = 0; t < nchunk; t++) {
        int b = t & 1;
        // convert + store current chunk into buffer b
        {
#pragma unroll
            for (int i = 0; i < 16; i += 2) {
                __nv_bfloat16 h0 = __float2bfloat16(av[i]);
                __nv_bfloat16 h1 = __float2bfloat16(av[i+1]);
                __nv_bfloat16 l0 = __float2bfloat16(av[i]   - __bfloat162float(h0));
                __nv_bfloat16 l1 = __float2bfloat16(av[i+1] - __bfloat162float(h1));
                uint32_t off = ar * SA_ST + (ah + i) * 2;
                *(uint32_t*)(sm + OFF_AHI(b) + off) = bfpack(h0, h1);
                *(uint32_t*)(sm + OFF_ALO(b) + off) = bfpack(l0, l1);
            }
#pragma unroll
            for (int i = 0; i < 8; i++) {
                __nv_bfloat16 h = __float2bfloat16(bv[i]);
                __nv_bfloat16 l = __float2bfloat16(bv[i] - __bfloat162float(h));
                uint32_t off = (bcol + i) * SA_ST + brow * 2;
                *(__nv_bfloat16*)(sm + OFF_BHI(b) + off) = h;
                *(__nv_bfloat16*)(sm + OFF_BLO(b) + off) = l;
            }
        }
        // prefetch next chunk into regs
        if (t + 1 < nchunk) {
            int kt = (t + 1) << 5;
            const float* ap = A + (long)(rowBase + ar) * lda + kt + ah;
#pragma unroll
            for (int i = 0; i < 4; i++) {
                float4 v = *(const float4*)(ap + i * 4);
                av[i*4+0]=v.x; av[i*4+1]=v.y; av[i*4+2]=v.z; av[i*4+3]=v.w;
            }
            const float* bp = Bm + (long)(kt + brow) * ldb + colBase + bcol;
#pragma unroll
            for (int i = 0; i < 8; i++)
                bv[i] = (colBase + bcol + i < N) ? bp[i] : 0.f;
        }
        __syncthreads();
        // ---- compute from buffer b ----
#pragma unroll
        for (int ks = 0; ks < 2; ks++) {
            uint32_t aHi[2][4], aLo[2][4], bHi[4][2], bLo[4][2];
#pragma unroll
            for (int ma = 0; ma < 2; ma++) {
                int r0 = warpRow * 32 + ma * 16 + g;
                uint32_t o0 = r0 * SA_ST + (ks * 16 + tg * 2) * 2;
                uint32_t o1 = (r0 + 8) * SA_ST + (ks * 16 + tg * 2) * 2;
                aHi[ma][0] = *(const uint32_t*)(sm + OFF_AHI(b) + o0);
                aHi[ma][1] = *(const uint32_t*)(sm + OFF_AHI(b) + o1);
                aHi[ma][2] = *(const uint32_t*)(sm + OFF_AHI(b) + o0 + 16);
                aHi[ma][3] = *(const uint32_t*)(sm + OFF_AHI(b) + o1 + 16);
                aLo[ma][0] = *(const uint32_t*)(sm + OFF_ALO(b) + o0);
                aLo[ma][1] = *(const uint32_t*)(sm + OFF_ALO(b) + o1);
                aLo[ma][2] = *(const uint32_t*)(sm + OFF_ALO(b) + o0 + 16);
                aLo[ma][3] = *(const uint32_t*)(sm + OFF_ALO(b) + o1 + 16);
            }
#pragma unroll
            for (int na = 0; na < 4; na++) {
                int n0 = warpCol * 32 + na * 8 + g;
                uint32_t o = n0 * SA_ST + (ks * 16 + tg * 2) * 2;
                bHi[na][0] = *(const uint32_t*)(sm + OFF_BHI(b) + o);
                bHi[na][1] = *(const uint32_t*)(sm + OFF_BHI(b) + o + 16);
                bLo[na][0] = *(const uint32_t*)(sm + OFF_BLO(b) + o);
                bLo[na][1] = *(const uint32_t*)(sm + OFF_BLO(b) + o + 16);
            }
#pragma unroll
            for (int ma = 0; ma < 2; ma++)
#pragma unroll
                for (int na = 0; na < 4; na++) {
                    mma16816(acc[ma][na], aHi[ma], bHi[na]);
                    mma16816(acc[ma][na], aHi[ma], bLo[na]);
                    mma16816(acc[ma][na], aLo[ma], bHi[na]);
                }
        }
        __syncthreads();   // protect buffer b before next iteration's store
    }

    // ---- epilogue ----
#pragma unroll
    for (int ma = 0; ma < 2; ma++) {
#pragma unroll
        for (int na = 0; na < 4; na++) {
            int col = colBase + warpCol * 32 + na * 8 + tg * 2;
            if (col < N) {
                int row0 = rowBase + warpRow * 32 + ma * 16 + g;
                float2 v0, v1;
                v0.x = acc[ma][na][0] + bias[col];
                v0.y = acc[ma][na][1] + bias[col + 1];
                v1.x = acc[ma][na][2] + bias[col];
                v1.y = acc[ma][na][3] + bias[col + 1];
                if (RELU) {
                    v0.x = fmaxf(v0.x, 0.f); v0.y = fmaxf(v0.y, 0.f);
                    v1.x = fmaxf(v1.x, 0.f); v1.y = fmaxf(v1.y, 0.f);
                }
                if (RESID) {
                    float2 r0 = *(const float2*)(Rm + (long)row0 * ldr + col);
                    float2 r1 = *(const float2*)(Rm + (long)(row0 + 8) * ldr + col);
                    v0.x += r0.x; v0.y += r0.y;
                    v1.x += r1.x; v1.y += r1.y;
                }
                *(float2*)(C + (long)row0 * ldc + col) = v0;
                *(float2*)(C + (long)(row0 + 8) * ldc + col) = v1;
            }
        }
    }
}

// ---------------- fused flash attention (one head, DH=32), f32x2 + 2-way KV split
__global__ __launch_bounds__(256)
void attn_kernel(int head_off) {
    __shared__ float buf[8192];          // 32 KB
    __shared__ float Cm[128], Cl[128];

    int tid = threadIdx.x;
    int qi = tid & 127;
    int sp = tid >> 7;                   // 0 or 1
    int b = blockIdx.y;
    int q = blockIdx.x * 128 + qi;

    const float* qp = g_qkv + ((long)(b * SS) + q) * 96;
    u64t qr2[16];
    const float scale = 0.03125f;        // 1/sqrt(1024)
    u64t s2 = pack2(scale, scale);
#pragma unroll
    for (int i = 0; i < 8; i++) {
        ulonglong2 v = *(const ulonglong2*)(qp + i * 4);
        qr2[2 * i + 0] = mul2(v.x, s2);
        qr2[2 * i + 1] = mul2(v.y, s2);
    }

    float m = -1e30f, l = 0.f;
    u64t o2[16];
#pragma unroll
    for (int i = 0; i < 16; i++) o2[i] = 0ULL;

    int r = qi >> 1;
    int half = qi & 1;

    for (int t = 0; t < 8; t++) {
        int kt0 = sp * 512 + t * 64;
        __syncthreads();
        {
            const float* kp = g_qkv + ((long)(b * SS) + kt0 + r) * 96;
            float* dk = &buf[(sp * 64 + r) * 32 + half * 16];
            float* dv = &buf[4096 + (sp * 64 + r) * 32 + half * 16];
#pragma unroll
            for (int w = 0; w < 4; w++) {
                *(float4*)(dk + w * 4) = *(const float4*)(kp + 32 + half * 16 + w * 4);
                *(float4*)(dv + w * 4) = *(const float4*)(kp + 64 + half * 16 + w * 4);
            }
        }
        __syncthreads();
#pragma unroll 2
        for (int j = 0; j < 64; j++) {
            const ulonglong2* kp2 = (const ulonglong2*)&buf[(sp * 64 + j) * 32];
            u64t sa = 0ULL, sb2 = 0ULL, sc2 = 0ULL, sd = 0ULL;
#pragma unroll
            for (int i = 0; i < 4; i++) {
                ulonglong2 k0 = kp2[2 * i];
                ulonglong2 k1 = kp2[2 * i + 1];
                sa = fma2(qr2[4 * i + 0], k0.x, sa);
                sb2 = fma2(qr2[4 * i + 1], k0.y, sb2);
                sc2 = fma2(qr2[4 * i + 2], k1.x, sc2);
                sd = fma2(qr2[4 * i + 3], k1.y, sd);
            }
            float2 sf = unpack2(add2(add2(sa, sb2), add2(sc2, sd)));
            float sc = sf.x + sf.y;
            float p;
            if (sc > m) {
                float cf = __expf(m - sc);
                l *= cf;
                u64t cf2 = pack2(cf, cf);
#pragma unroll
                for (int i = 0; i < 16; i++) o2[i] = mul2(o2[i], cf2);
                m = sc;
                p = 1.f;
            } else {
                p = __expf(sc - m);
            }
            l += p;
            u64t pp = pack2(p, p);
            const ulonglong2* vp2 = (const ulonglong2*)&buf[4096 + (sp * 64 + j) * 32];
#pragma unroll
            for (int i = 0; i < 8; i++) {
                ulonglong2 v = vp2[i];
                o2[2 * i + 0] = fma2(pp, v.x, o2[2 * i + 0]);
                o2[2 * i + 1] = fma2(pp, v.y, o2[2 * i + 1]);
            }
        }
    }

    __syncthreads();
    if (sp == 1) {
        Cm[qi] = m; Cl[qi] = l;
        float* co = &buf[qi * 32];
#pragma unroll
        for (int i = 0; i < 16; i++) {
            float2 v = unpack2(o2[i]);
            co[2 * i] = v.x; co[2 * i + 1] = v.y;
        }
    }
    __syncthreads();
    if (sp == 0) {
        float m1 = Cm[qi], l1 = Cl[qi];
        float M = fmaxf(m, m1);
        float c0 = __expf(m - M);
        float c1 = __expf(m1 - M);
        float inv = 1.f / (c0 * l + c1 * l1);
        const float* co = &buf[qi * 32];
        float* op = g_heads + ((long)(b * SS) + q) * DD + head_off;
#pragma unroll
        for (int i = 0; i < 16; i++) {
            float2 v = unpack2(o2[i]);
            op[2 * i]     = (c0 * v.x + c1 * co[2 * i]) * inv;
            op[2 * i + 1] = (c0 * v.y + c1 * co[2 * i + 1]) * inv;
        }
    }
}

// ---------------- LayerNorm (in place), warp per row -------------------------
__global__ __launch_bounds__(256)
void ln_kernel(float* __restrict__ X, const float* __restrict__ g,
               const float* __restrict__ bb) {
    int warp = threadIdx.x >> 5;
    int lane = threadIdx.x & 31;
    int row = blockIdx.x * 8 + warp;
    float* xp = X + (long)row * DD;
    float v[16];
    float sum = 0.f;
#pragma unroll
    for (int w = 0; w < 4; w++) {
        float4 t = *(const float4*)(xp + lane * 4 + w * 128);
        v[w * 4 + 0] = t.x; v[w * 4 + 1] = t.y;
        v[w * 4 + 2] = t.z; v[w * 4 + 3] = t.w;
        sum += (t.x + t.y) + (t.z + t.w);
    }
#pragma unroll
    for (int off = 16; off; off >>= 1) sum += __shfl_xor_sync(~0u, sum, off);
    float mean = sum * (1.f / (float)DD);
    float var = 0.f;
#pragma unroll
    for (int i = 0; i < 16; i++) {
        float d = v[i] - mean;
        var += d * d;
    }
#pragma unroll
    for (int off = 16; off; off >>= 1) var += __shfl_xor_sync(~0u, var, off);
    var *= (1.f / (float)DD);
    float rs = rsqrtf(var + 1e-3f);
#pragma unroll
    for (int w = 0; w < 4; w++) {
#pragma unroll
        for (int j = 0; j < 4; j++) {
            int d = lane * 4 + w * 128 + j;
            xp[d] = (v[w * 4 + j] - mean) * rs * g[d] + bb[d];
        }
    }
}

// ---------------- mean-pool over S, final dense + sigmoid --------------------
__global__ __launch_bounds__(256)
void pool_kernel(const float* __restrict__ Wf, const float* __restrict__ bf,
                 float* __restrict__ out) {
    int b = blockIdx.x;
    const float* xp = g_x + (long)b * SS * DD;
    float partial = 0.f;
    for (int i = threadIdx.x; i < SS * DD; i += blockDim.x)
        partial += xp[i] * Wf[i & (DD - 1)];
    __shared__ float red[256];
    red[threadIdx.x] = partial;
    __syncthreads();
    for (int s = 128; s; s >>= 1) {
        if (threadIdx.x < s) red[threadIdx.x] += red[threadIdx.x + s];
        __syncthreads();
    }
    if (threadIdx.x == 0) {
        float z = red[0] * (1.f / (float)SS) + bf[0];
        out[b] = z;
        out[BB + b] = 1.f / (1.f + expf(-z));
    }
}

// ---------------- host orchestration -----------------------------------------
extern "C" void kernel_launch(void* const* d_in, const int* in_sizes, int n_in,
                              void* d_out, int out_size) {
    const int*   tokens = (const int*)  d_in[0];
    const float* emb    = (const float*)d_in[1];
    const float* W0     = (const float*)d_in[2];
    const float* b0     = (const float*)d_in[3];
    const float* Wh     = (const float*)d_in[4];
    const float* bh     = (const float*)d_in[5];
    const float* Wo     = (const float*)d_in[6];
    const float* bo     = (const float*)d_in[7];
    const float* g1     = (const float*)d_in[8];
    const float* be1    = (const float*)d_in[9];
    const float* W1     = (const float*)d_in[10];
    const float* b1     = (const float*)d_in[11];
    const float* W2     = (const float*)d_in[12];
    const float* b2     = (const float*)d_in[13];
    const float* g2     = (const float*)d_in[14];
    const float* be2    = (const float*)d_in[15];
    const float* Wf     = (const float*)d_in[16];
    const float* bf     = (const float*)d_in[17];
    float* out = (float*)d_out;

    float *gx, *gy, *gh, *gq, *gf;
    cudaGetSymbolAddress((void**)&gx, g_x);
    cudaGetSymbolAddress((void**)&gy, g_y);
    cudaGetSymbolAddress((void**)&gh, g_heads);
    cudaGetSymbolAddress((void**)&gq, g_qkv);
    cudaGetSymbolAddress((void**)&gf, g_ff);

    cudaFuncSetAttribute(gemm_tc<false, false>,
                         cudaFuncAttributeMaxDynamicSharedMemorySize, SMEM_GT);
    cudaFuncSetAttribute(gemm_tc<true, false>,
                         cudaFuncAttributeMaxDynamicSharedMemorySize, SMEM_GT);
    cudaFuncSetAttribute(gemm_tc<false, true>,
                         cudaFuncAttributeMaxDynamicSharedMemorySize, SMEM_GT);

    const int MTILES = MR / 128;   // 256

    embed_kernel<<<MR, 128>>>(tokens, emb);

    for (int l = 0; l < NBLK; l++) {
        // head 0 QKV: [MR,512] @ [512,96]
        gemm_tc<false, false><<<dim3(2, MTILES), 256, SMEM_GT>>>(
            gx, DD, W0 + (long)l * DD * 96, 96, b0 + (long)l * 96,
            nullptr, 0, gq, 96, 96, DD);
        attn_kernel<<<dim3(SS / 128, BB), 256>>>(0);

        // chained heads 1..15: [MR,32] @ [32,96]
        for (int i = 0; i < NHEAD - 1; i++) {
            gemm_tc<false, false><<<dim3(2, MTILES), 256, SMEM_GT>>>(
                gh + i * DHD, DD,
                Wh + ((long)l * (NHEAD - 1) + i) * DHD * 96, 96,
                bh + ((long)l * (NHEAD - 1) + i) * 96,
                nullptr, 0, gq, 96, 96, DHD);
            attn_kernel<<<dim3(SS / 128, BB), 256>>>((i + 1) * DHD);
        }

        // output projection + residual
        gemm_tc<false, true><<<dim3(DD / 64, MTILES), 256, SMEM_GT>>>(
            gh, DD, Wo + (long)l * DD * DD, DD, bo + (long)l * DD,
            gx, DD, gy, DD, DD, DD);
        ln_kernel<<<MR / 8, 256>>>(gy, g1 + (long)l * DD, be1 + (long)l * DD);

        // FFN
        gemm_tc<true, false><<<dim3(FFD / 64, MTILES), 256, SMEM_GT>>>(
            gy, DD, W1 + (long)l * DD * FFD, FFD, b1 + (long)l * FFD,
            nullptr, 0, gf, FFD, FFD, DD);
        gemm_tc<false, true><<<dim3(DD / 64, MTILES), 256, SMEM_GT>>>(
            gf, FFD, W2 + (long)l * FFD * DD, DD, b2 + (long)l * DD,
            gy, DD, gx, DD, DD, FFD);
        ln_kernel<<<MR / 8, 256>>>(gx, g2 + (long)l * DD, be2 + (long)l * DD);
    }

    pool_kernel<<<BB, 256>>>(Wf, bf, out);
}